// round 15
// baseline (speedup 1.0000x reference)
#include <cuda_runtime.h>
#include <cuda_fp16.h>
#include <cstdint>

// Problem constants (fixed by the reference)
#define BB 8
#define CC 128
#define HH 128
#define WW 128
#define PP 32768
#define HW (HH * WW)

// Binning: 8x8 spatial tiles -> 16x16 tiles per batch, 2048 bins total.
#define TILE 8
#define TPD (WW / TILE)            // 16
#define BINS_PER_B (TPD * TPD)     // 256
#define NBINS (BB * BINS_PER_B)    // 2048
#define CAP 320                    // bin capacity (mean ~120)
#define OOBCAP 65536               // OOB list capacity (~16K expected)

#define WIN 9                      // 9x9 corner window per bin

__device__ int g_count[NBINS + 1];              // per-bin counts + [NBINS]=oob
__device__ unsigned g_binned[NBINS * CAP];      // point indices per bin
__device__ unsigned g_oob[OOBCAP];              // out-of-bounds point indices

static __device__ __forceinline__ __half2 u32_to_h2(unsigned u) {
    return *reinterpret_cast<__half2*>(&u);
}

// ---------------------------------------------------------------------------
// Kernel A: zero bin counters
// ---------------------------------------------------------------------------
__global__ void zero_counts_kernel() {
    const int i = blockIdx.x * 256 + threadIdx.x;
    if (i < NBINS + 1) g_count[i] = 0;
}

// ---------------------------------------------------------------------------
// Kernel B: bin points by spatial tile (in-bounds) or OOB list.
// ---------------------------------------------------------------------------
__global__ __launch_bounds__(256) void bin_kernel(const float* __restrict__ tk_codes) {
    const unsigned FULL = 0xffffffffu;
    const int pidx = blockIdx.x * 256 + threadIdx.x;
    const int lane = threadIdx.x & 31;

    const float2 pt = __ldg(((const float2*)tk_codes) + pidx);
    const float x = pt.x, y = pt.y;
    const bool inb = (x >= 0.0f) & (y >= 0.0f) &
                     (x <= (float)(WW - 1)) & (y <= (float)(HH - 1));

    const unsigned oob_mask = __ballot_sync(FULL, !inb);
    if (inb) {
        const int fxI = (int)floorf(x);
        const int fyI = (int)floorf(y);
        const int tile = (pidx >> 15) * BINS_PER_B + (fyI >> 3) * TPD + (fxI >> 3);
        const int slot = atomicAdd(&g_count[tile], 1);
        if (slot < CAP) g_binned[tile * CAP + slot] = (unsigned)pidx;
    } else {
        const int leader = __ffs(oob_mask) - 1;
        int base = 0;
        if (lane == leader) base = atomicAdd(&g_count[NBINS], __popc(oob_mask));
        base = __shfl_sync(oob_mask, base, leader);
        const int off = __popc(oob_mask & ((1u << lane) - 1));
        if (base + off < OOBCAP) g_oob[base + off] = (unsigned)pidx;
    }
}

// ---------------------------------------------------------------------------
// Kernel C: fused window-gather. One block per bin. Loads the bin's 9x9x128
// f32 window directly from feat [B,C,H,W] into smem as [y][x][c2] fp16
// (20.7KB), then gathers with conflict-free LDS. No global transpose needed.
// ---------------------------------------------------------------------------
__global__ __launch_bounds__(256) void fused_gather_kernel(
    const float* __restrict__ tk_codes,   // [B, P, 2]
    const float* __restrict__ feat,       // [B, C, H, W]
    float* __restrict__ out)              // [B, P, C]
{
    __shared__ __half2 win[WIN * WIN * 64];   // [y][x][c2], 20736 B

    const unsigned FULL = 0xffffffffu;
    const int bin = blockIdx.x;
    const int warp = threadIdx.x >> 5;
    const int lane = threadIdx.x & 31;

    int npts = g_count[bin];
    if (npts > CAP) npts = CAP;
    if (npts == 0) return;

    const int batch = bin >> 8;
    const int tloc = bin & 255;
    const int x0 = (tloc & 15) * TILE;
    const int y0 = (tloc >> 4) * TILE;

    const float* __restrict__ fb = feat + (size_t)batch * CC * HW;

    // ---- stage window: tasks = 64 c2-pairs x 9 y-rows = 576 ----
    for (int t = threadIdx.x; t < 64 * WIN; t += 256) {
        const int c2 = t & 63;
        const int yy = t >> 6;                       // 0..8
        const int y = min(y0 + yy, HH - 1);
        const float* r0 = fb + ((size_t)(2 * c2) * HH + y) * WW + x0;
        const float* r1 = fb + ((size_t)(2 * c2 + 1) * HH + y) * WW + x0;
        const float4 a0 = *(const float4*)r0;        // x0 is 32B-aligned
        const float4 a1 = *(const float4*)(r0 + 4);
        const float4 b0 = *(const float4*)r1;
        const float4 b1 = *(const float4*)(r1 + 4);
        const int x8 = min(x0 + 8, WW - 1) - x0;     // 9th x (clamped; unused at edge)
        const float a8 = r0[x8];
        const float b8 = r1[x8];

        __half2* wr = win + (size_t)yy * (WIN * 64) + c2;
        wr[0 * 64] = __floats2half2_rn(a0.x, b0.x);
        wr[1 * 64] = __floats2half2_rn(a0.y, b0.y);
        wr[2 * 64] = __floats2half2_rn(a0.z, b0.z);
        wr[3 * 64] = __floats2half2_rn(a0.w, b0.w);
        wr[4 * 64] = __floats2half2_rn(a1.x, b1.x);
        wr[5 * 64] = __floats2half2_rn(a1.y, b1.y);
        wr[6 * 64] = __floats2half2_rn(a1.z, b1.z);
        wr[7 * 64] = __floats2half2_rn(a1.w, b1.w);
        wr[8 * 64] = __floats2half2_rn(a8, b8);
    }
    __syncthreads();

    // ---- gather: 8 warps x 8 points per pass ----
    const unsigned* __restrict__ blist = g_binned + (size_t)bin * CAP;
    float4* __restrict__ o4 = (float4*)out;

    const int j = lane >> 2;                 // this lane's point (0..7)
    const int k = lane & 3;                  // this lane's corner

    for (int base = warp * 8; base < npts; base += 64) {
        const int myp = base + j;
        const unsigned pidx = blist[(myp < npts) ? myp : 0];

        const float2 pt = __ldg(((const float2*)tk_codes) + pidx);
        const float x = pt.x, y = pt.y;

        // binned points are in-bounds: fmod/max/in-bounds mask are identities
        const float cxk = (k & 2) ? ceilf(x) : floorf(x);
        const float cyk = (k & 1) ? ceilf(y) : floorf(y);
        const int gx = (int)cxk;
        const int gy = (int)cyk;

        const float dx = x - (float)gx;
        const float dy = y - (float)gy;
        float w = __fdividef(1.0f, sqrtf(dx * dx + dy * dy) + 1e-10f);

        float d = w + __shfl_xor_sync(FULL, w, 1);
        d += __shfl_xor_sync(FULL, d, 2);            // d > 0 always (in-bounds)
        w *= __fdividef(1.0f, d);

        const int iL = (gy - y0) * WIN + (gx - x0);  // 0..80
        const unsigned wbits = (unsigned)__half_as_ushort(__float2half_rn(w));
        const unsigned packed = (wbits << 16) | (unsigned)iL;

        const int nhere = min(8, npts - base);
#pragma unroll
        for (int p = 0; p < 8; p++) {
            if (p >= nhere) break;
            const int s = p * 4;
            const unsigned v0 = __shfl_sync(FULL, packed, s + 0);
            const unsigned v1 = __shfl_sync(FULL, packed, s + 1);
            const unsigned v2 = __shfl_sync(FULL, packed, s + 2);
            const unsigned v3 = __shfl_sync(FULL, packed, s + 3);
            const unsigned pout = __shfl_sync(FULL, pidx, s);

            const __half2 w0 = u32_to_h2(__byte_perm(v0, v0, 0x3232));
            const __half2 w1 = u32_to_h2(__byte_perm(v1, v1, 0x3232));
            const __half2 w2 = u32_to_h2(__byte_perm(v2, v2, 0x3232));
            const __half2 w3 = u32_to_h2(__byte_perm(v3, v3, 0x3232));
            const int i0 = (int)(v0 & 0xFFFFu);
            const int i1 = (int)(v1 & 0xFFFFu);
            const int i2 = (int)(v2 & 0xFFFFu);
            const int i3 = (int)(v3 & 0xFFFFu);

            // conflict-free LDS.64: lane covers channels [4*lane, 4*lane+4)
            const uint2 r0 = *(const uint2*)(win + i0 * 64 + 2 * lane);
            const uint2 r1 = *(const uint2*)(win + i1 * 64 + 2 * lane);
            const uint2 r2 = *(const uint2*)(win + i2 * 64 + 2 * lane);
            const uint2 r3 = *(const uint2*)(win + i3 * 64 + 2 * lane);

            __half2 a0 = __hmul2(w0, u32_to_h2(r0.x));
            __half2 a1 = __hmul2(w0, u32_to_h2(r0.y));
            a0 = __hfma2(w1, u32_to_h2(r1.x), a0);
            a1 = __hfma2(w1, u32_to_h2(r1.y), a1);
            a0 = __hfma2(w2, u32_to_h2(r2.x), a0);
            a1 = __hfma2(w2, u32_to_h2(r2.y), a1);
            a0 = __hfma2(w3, u32_to_h2(r3.x), a0);
            a1 = __hfma2(w3, u32_to_h2(r3.y), a1);

            const float2 f0 = __half22float2(a0);
            const float2 f1 = __half22float2(a1);
            __stcs(o4 + (size_t)pout * 32 + lane,
                   make_float4(f0.x, f0.y, f1.x, f1.y));
        }
    }
}

// ---------------------------------------------------------------------------
// Kernel D: zero the output rows of out-of-bounds points (weights all 0).
// ---------------------------------------------------------------------------
__global__ __launch_bounds__(256) void zero_oob_kernel(float* __restrict__ out) {
    const int lane = threadIdx.x & 31;
    const int gwarp = (blockIdx.x * blockDim.x + threadIdx.x) >> 5;
    const int nwarps = (gridDim.x * blockDim.x) >> 5;

    int noob = g_count[NBINS];
    if (noob > OOBCAP) noob = OOBCAP;

    float4* __restrict__ o4 = (float4*)out;
    const float4 z = make_float4(0.f, 0.f, 0.f, 0.f);
    for (int i = gwarp; i < noob; i += nwarps) {
        const unsigned pidx = g_oob[i];
        __stcs(o4 + (size_t)pidx * 32 + lane, z);
    }
}

// ---------------------------------------------------------------------------
extern "C" void kernel_launch(void* const* d_in, const int* in_sizes, int n_in,
                              void* d_out, int out_size) {
    const float* tk_codes = (const float*)d_in[0];   // [B, P, 2] float32
    const float* feat     = (const float*)d_in[1];   // [B, C, H, W] float32
    float* out            = (float*)d_out;           // [B, P, C] float32

    (void)in_sizes; (void)n_in; (void)out_size;

    zero_counts_kernel<<<(NBINS + 256) / 256, 256>>>();
    bin_kernel<<<(BB * PP) / 256, 256>>>(tk_codes);
    fused_gather_kernel<<<NBINS, 256>>>(tk_codes, feat, out);
    zero_oob_kernel<<<64, 256>>>(out);
}

// round 16
// speedup vs baseline: 1.8665x; 1.8665x over previous
#include <cuda_runtime.h>
#include <cuda_fp16.h>
#include <cstdint>

// Problem constants (fixed by the reference)
#define BB 8
#define CC 128
#define HH 128
#define WW 128
#define PP 32768
#define HW (HH * WW)

// Scratch: feat_grid transposed to [B, H*W, C] channels-last, fp16. 33.5 MB.
__device__ __half g_featT[BB * HW * CC];

// bit-cast helpers
static __device__ __forceinline__ unsigned h2_to_u32(__half2 h) {
    return *reinterpret_cast<unsigned*>(&h);
}
static __device__ __forceinline__ __half2 u32_to_h2(unsigned u) {
    return *reinterpret_cast<__half2*>(&u);
}

// ---------------------------------------------------------------------------
// Kernel 1: tiled transpose + f32->fp16:  src[C][HW] -> dstT[HW][C] (half)
// Tile: 32 channels x 128 hw. grid: (HW/128, CC/32, B), block: (32, 8).
// Signals PDL launch_dependents after its stores so the gather can ramp up.
// ---------------------------------------------------------------------------
__global__ void transpose_kernel(const float* __restrict__ src) {
    __shared__ float tile[32][129];

    const int b = blockIdx.z;
    const int hw0 = blockIdx.x * 128;
    const int c0 = blockIdx.y * 32;
    const float* sb = src + (size_t)b * CC * HW;
    __half2* db = (__half2*)(g_featT + (size_t)b * HW * CC);

    const int tx = threadIdx.x, ty = threadIdx.y;

    // read: each thread loads 4 float4 (rows c0+ty+8j, cols hw0+4tx..)
#pragma unroll
    for (int jj = 0; jj < 4; jj++) {
        const int c = ty + jj * 8;
        const float4 v = __ldcs((const float4*)&sb[(size_t)(c0 + c) * HW + hw0] + tx);
        tile[c][4 * tx + 0] = v.x;
        tile[c][4 * tx + 1] = v.y;
        tile[c][4 * tx + 2] = v.z;
        tile[c][4 * tx + 3] = v.w;
    }
    __syncthreads();

    // write: thread t -> h2 col (t&15), row group (t>>4); 8 passes of 16 rows
    const int t = ty * 32 + tx;
    const int col = t & 15;
    const int rowg = t >> 4;
#pragma unroll
    for (int pass = 0; pass < 8; pass++) {
        const int row = rowg + pass * 16;
        const float lo = tile[2 * col][row];
        const float hi = tile[2 * col + 1][row];
        db[(size_t)(hw0 + row) * (CC / 2) + (c0 >> 1) + col] =
            __floats2half2_rn(lo, hi);
    }

    // PDL: this block's featT writes are done; release dependents.
    asm volatile("griddepcontrol.launch_dependents;");
}

// ---------------------------------------------------------------------------
// Kernel 2: EIGHT points per warp, all 32 lanes = unique (point, corner)
// slot. Prologue (coord load + weight math) runs under PDL overlap; the
// griddepcontrol.wait sits immediately before the first featT access.
// ---------------------------------------------------------------------------
__global__ __launch_bounds__(256) void gather_kernel(
    const float* __restrict__ tk_codes,   // [B, P, 2]
    float* __restrict__ out)              // [B, P, C]
{
    const unsigned FULL = 0xffffffffu;
    const int oct = (blockIdx.x * blockDim.x + threadIdx.x) >> 5;  // 8-point group
    const int lane = threadIdx.x & 31;

    const int p0 = oct * 8;                  // first point of this warp's group
    const int j = lane >> 2;                 // this lane's point (0..7)
    const int k = lane & 3;                  // this lane's corner

    // ---- prologue: independent of featT (overlaps transpose via PDL) ----
    const float2 pt = __ldg(((const float2*)tk_codes) + p0 + j);
    const float x = pt.x;
    const float y = pt.y;

    const bool inb = (x >= 0.0f) & (y >= 0.0f) &
                     (x <= (float)(WW - 1)) & (y <= (float)(HH - 1));

    // corner order: (fx,fy),(fx,cy),(cx,fy),(cx,cy)
    const float cxk = (k & 2) ? ceilf(x) : floorf(x);
    const float cyk = (k & 1) ? ceilf(y) : floorf(y);

    int gx = ((int)cxk) % WW;   // C-style %: matches jnp.fmod on int32
    int gy = ((int)cyk) % HH;
    gx = max(gx, 0);
    gy = max(gy, 0);

    const float dx = x - (float)gx;
    const float dy = y - (float)gy;
    float w = inb ? __fdividef(1.0f, sqrtf(dx * dx + dy * dy) + 1e-10f) : 0.0f;

    // butterfly within each 4-lane corner group
    float d = w + __shfl_xor_sync(FULL, w, 1);
    d += __shfl_xor_sync(FULL, d, 2);
    if (d == 0.0f) d = 1.0f;
    w *= __fdividef(1.0f, d);               // normalized weight in [0,1]

    const int idx = (gy << 7) + gx;
    const unsigned hw2 = h2_to_u32(__float2half2_rn(w));

    const int b = p0 >> 15;                  // P = 32768; group never spans batches
    const uint2* __restrict__ baseT =
        (const uint2*)(g_featT + (size_t)b * HW * CC);
    float4* __restrict__ o4 = (float4*)out;

    // ---- PDL: wait for the transpose's featT writes before reading ----
    asm volatile("griddepcontrol.wait;" ::: "memory");

#pragma unroll
    for (int p = 0; p < 8; p++) {
        const int s = p * 4;
        const __half2 w0 = u32_to_h2(__shfl_sync(FULL, hw2, s + 0));
        const __half2 w1 = u32_to_h2(__shfl_sync(FULL, hw2, s + 1));
        const __half2 w2 = u32_to_h2(__shfl_sync(FULL, hw2, s + 2));
        const __half2 w3 = u32_to_h2(__shfl_sync(FULL, hw2, s + 3));
        const int i0 = __shfl_sync(FULL, idx, s + 0);
        const int i1 = __shfl_sync(FULL, idx, s + 1);
        const int i2 = __shfl_sync(FULL, idx, s + 2);
        const int i3 = __shfl_sync(FULL, idx, s + 3);

        const uint2 r0 = baseT[(size_t)i0 * 32 + lane];
        const uint2 r1 = baseT[(size_t)i1 * 32 + lane];
        const uint2 r2 = baseT[(size_t)i2 * 32 + lane];
        const uint2 r3 = baseT[(size_t)i3 * 32 + lane];

        __half2 a0 = __hmul2(w0, u32_to_h2(r0.x));
        __half2 a1 = __hmul2(w0, u32_to_h2(r0.y));
        a0 = __hfma2(w1, u32_to_h2(r1.x), a0);
        a1 = __hfma2(w1, u32_to_h2(r1.y), a1);
        a0 = __hfma2(w2, u32_to_h2(r2.x), a0);
        a1 = __hfma2(w2, u32_to_h2(r2.y), a1);
        a0 = __hfma2(w3, u32_to_h2(r3.x), a0);
        a1 = __hfma2(w3, u32_to_h2(r3.y), a1);

        const float2 f0 = __half22float2(a0);
        const float2 f1 = __half22float2(a1);
        __stcs(o4 + (size_t)(p0 + p) * 32 + lane,
               make_float4(f0.x, f0.y, f1.x, f1.y));
    }
}

// ---------------------------------------------------------------------------
extern "C" void kernel_launch(void* const* d_in, const int* in_sizes, int n_in,
                              void* d_out, int out_size) {
    const float* tk_codes = (const float*)d_in[0];   // [B, P, 2] float32
    const float* feat     = (const float*)d_in[1];   // [B, C, H, W] float32
    float* out            = (float*)d_out;           // [B, P, C] float32

    (void)in_sizes; (void)n_in; (void)out_size;

    dim3 tgrid(HW / 128, CC / 32, BB);
    dim3 tblock(32, 8);
    transpose_kernel<<<tgrid, tblock>>>(feat);

    // gather with Programmatic Dependent Launch: may begin ramping while the
    // transpose drains; the in-kernel griddepcontrol.wait enforces ordering.
    const int total_octs = BB * PP / 8;          // 32768 groups, 1 warp each
    const int gblocks = (total_octs * 32) / 256;

    cudaLaunchConfig_t cfg = {};
    cfg.gridDim = dim3(gblocks);
    cfg.blockDim = dim3(256);
    cfg.dynamicSmemBytes = 0;
    cfg.stream = 0;
    cudaLaunchAttribute attrs[1];
    attrs[0].id = cudaLaunchAttributeProgrammaticStreamSerialization;
    attrs[0].val.programmaticStreamSerializationAllowed = 1;
    cfg.attrs = attrs;
    cfg.numAttrs = 1;
    cudaLaunchKernelEx(&cfg, gather_kernel, tk_codes, out);
}

// round 17
// speedup vs baseline: 1.9456x; 1.0423x over previous
#include <cuda_runtime.h>
#include <cuda_fp16.h>
#include <cstdint>

// Problem constants (fixed by the reference)
#define BB 8
#define CC 128
#define HH 128
#define WW 128
#define PP 32768
#define HW (HH * WW)

// Scratch: feat_grid transposed to [B, H*W, C] channels-last, fp16. 33.5 MB.
__device__ __half g_featT[BB * HW * CC];

// bit-cast helpers
static __device__ __forceinline__ unsigned h2_to_u32(__half2 h) {
    return *reinterpret_cast<unsigned*>(&h);
}
static __device__ __forceinline__ __half2 u32_to_h2(unsigned u) {
    return *reinterpret_cast<__half2*>(&u);
}

// ---------------------------------------------------------------------------
// Kernel 1: tiled transpose + f32->fp16:  src[C][HW] -> dstT[HW][C] (half)
// Tile: 32 channels x 128 hw. grid: (HW/128, CC/32, B), block: (32, 8).
// Staging: stride-32 scalar loads -> STS bank = (c + tx) mod 32, conflict-free
// (the float4 variant had a 4-way STS conflict at columns 4tx+i).
// ---------------------------------------------------------------------------
__global__ void transpose_kernel(const float* __restrict__ src) {
    __shared__ float tile[32][129];

    const int b = blockIdx.z;
    const int hw0 = blockIdx.x * 128;
    const int c0 = blockIdx.y * 32;
    const float* sb = src + (size_t)b * CC * HW;
    __half2* db = (__half2*)(g_featT + (size_t)b * HW * CC);

    const int tx = threadIdx.x, ty = threadIdx.y;

    // read: 16 coalesced 128B loads per warp-row; conflict-free STS
#pragma unroll
    for (int jj = 0; jj < 4; jj++) {
        const int c = ty + jj * 8;
        const float* row = &sb[(size_t)(c0 + c) * HW + hw0];
#pragma unroll
        for (int m = 0; m < 4; m++) {
            tile[c][tx + 32 * m] = __ldcs(row + tx + 32 * m);
        }
    }
    __syncthreads();

    // write: thread t -> h2 col (t&15), row group (t>>4); 8 passes of 16 rows
    // (banks: lanes 0-15 even, 16-31 odd -> conflict-free)
    const int t = ty * 32 + tx;
    const int col = t & 15;
    const int rowg = t >> 4;
#pragma unroll
    for (int pass = 0; pass < 8; pass++) {
        const int row = rowg + pass * 16;
        const float lo = tile[2 * col][row];
        const float hi = tile[2 * col + 1][row];
        db[(size_t)(hw0 + row) * (CC / 2) + (c0 >> 1) + col] =
            __floats2half2_rn(lo, hi);
    }

    // PDL: this block's featT writes are done; release dependents.
    asm volatile("griddepcontrol.launch_dependents;");
}

// ---------------------------------------------------------------------------
// Kernel 2: EIGHT points per warp, all 32 lanes = unique (point, corner)
// slot. Prologue (coord load + weight math) runs under PDL overlap; the
// griddepcontrol.wait sits immediately before the first featT access.
// ---------------------------------------------------------------------------
__global__ __launch_bounds__(256) void gather_kernel(
    const float* __restrict__ tk_codes,   // [B, P, 2]
    float* __restrict__ out)              // [B, P, C]
{
    const unsigned FULL = 0xffffffffu;
    const int oct = (blockIdx.x * blockDim.x + threadIdx.x) >> 5;  // 8-point group
    const int lane = threadIdx.x & 31;

    const int p0 = oct * 8;                  // first point of this warp's group
    const int j = lane >> 2;                 // this lane's point (0..7)
    const int k = lane & 3;                  // this lane's corner

    // ---- prologue: independent of featT (overlaps transpose via PDL) ----
    const float2 pt = __ldg(((const float2*)tk_codes) + p0 + j);
    const float x = pt.x;
    const float y = pt.y;

    const bool inb = (x >= 0.0f) & (y >= 0.0f) &
                     (x <= (float)(WW - 1)) & (y <= (float)(HH - 1));

    // corner order: (fx,fy),(fx,cy),(cx,fy),(cx,cy)
    const float cxk = (k & 2) ? ceilf(x) : floorf(x);
    const float cyk = (k & 1) ? ceilf(y) : floorf(y);

    int gx = ((int)cxk) % WW;   // C-style %: matches jnp.fmod on int32
    int gy = ((int)cyk) % HH;
    gx = max(gx, 0);
    gy = max(gy, 0);

    const float dx = x - (float)gx;
    const float dy = y - (float)gy;
    float w = inb ? __fdividef(1.0f, sqrtf(dx * dx + dy * dy) + 1e-10f) : 0.0f;

    // butterfly within each 4-lane corner group
    float d = w + __shfl_xor_sync(FULL, w, 1);
    d += __shfl_xor_sync(FULL, d, 2);
    if (d == 0.0f) d = 1.0f;
    w *= __fdividef(1.0f, d);               // normalized weight in [0,1]

    const int idx = (gy << 7) + gx;
    const unsigned hw2 = h2_to_u32(__float2half2_rn(w));

    const int b = p0 >> 15;                  // P = 32768; group never spans batches
    const uint2* __restrict__ baseT =
        (const uint2*)(g_featT + (size_t)b * HW * CC);
    float4* __restrict__ o4 = (float4*)out;

    // ---- PDL: wait for the transpose's featT writes before reading ----
    asm volatile("griddepcontrol.wait;" ::: "memory");

#pragma unroll
    for (int p = 0; p < 8; p++) {
        const int s = p * 4;
        const __half2 w0 = u32_to_h2(__shfl_sync(FULL, hw2, s + 0));
        const __half2 w1 = u32_to_h2(__shfl_sync(FULL, hw2, s + 1));
        const __half2 w2 = u32_to_h2(__shfl_sync(FULL, hw2, s + 2));
        const __half2 w3 = u32_to_h2(__shfl_sync(FULL, hw2, s + 3));
        const int i0 = __shfl_sync(FULL, idx, s + 0);
        const int i1 = __shfl_sync(FULL, idx, s + 1);
        const int i2 = __shfl_sync(FULL, idx, s + 2);
        const int i3 = __shfl_sync(FULL, idx, s + 3);

        const uint2 r0 = baseT[(size_t)i0 * 32 + lane];
        const uint2 r1 = baseT[(size_t)i1 * 32 + lane];
        const uint2 r2 = baseT[(size_t)i2 * 32 + lane];
        const uint2 r3 = baseT[(size_t)i3 * 32 + lane];

        __half2 a0 = __hmul2(w0, u32_to_h2(r0.x));
        __half2 a1 = __hmul2(w0, u32_to_h2(r0.y));
        a0 = __hfma2(w1, u32_to_h2(r1.x), a0);
        a1 = __hfma2(w1, u32_to_h2(r1.y), a1);
        a0 = __hfma2(w2, u32_to_h2(r2.x), a0);
        a1 = __hfma2(w2, u32_to_h2(r2.y), a1);
        a0 = __hfma2(w3, u32_to_h2(r3.x), a0);
        a1 = __hfma2(w3, u32_to_h2(r3.y), a1);

        const float2 f0 = __half22float2(a0);
        const float2 f1 = __half22float2(a1);
        __stcs(o4 + (size_t)(p0 + p) * 32 + lane,
               make_float4(f0.x, f0.y, f1.x, f1.y));
    }
}

// ---------------------------------------------------------------------------
extern "C" void kernel_launch(void* const* d_in, const int* in_sizes, int n_in,
                              void* d_out, int out_size) {
    const float* tk_codes = (const float*)d_in[0];   // [B, P, 2] float32
    const float* feat     = (const float*)d_in[1];   // [B, C, H, W] float32
    float* out            = (float*)d_out;           // [B, P, C] float32

    (void)in_sizes; (void)n_in; (void)out_size;

    dim3 tgrid(HW / 128, CC / 32, BB);
    dim3 tblock(32, 8);
    transpose_kernel<<<tgrid, tblock>>>(feat);

    // gather with Programmatic Dependent Launch
    const int total_octs = BB * PP / 8;          // 32768 groups, 1 warp each
    const int gblocks = (total_octs * 32) / 256;

    cudaLaunchConfig_t cfg = {};
    cfg.gridDim = dim3(gblocks);
    cfg.blockDim = dim3(256);
    cfg.dynamicSmemBytes = 0;
    cfg.stream = 0;
    cudaLaunchAttribute attrs[1];
    attrs[0].id = cudaLaunchAttributeProgrammaticStreamSerialization;
    attrs[0].val.programmaticStreamSerializationAllowed = 1;
    cfg.attrs = attrs;
    cfg.numAttrs = 1;
    cudaLaunchKernelEx(&cfg, gather_kernel, tk_codes, out);
}